// round 9
// baseline (speedup 1.0000x reference)
#include <cuda_runtime.h>
#include <cuda_bf16.h>
#include <cstdint>

#define N_NODES 50000
#define N_EDGES 500000
#define HIDDEN  128
#define HEADS   8
#define HDIM    16

// ---------------- static device scratch ----------------
__device__ float g_q[N_NODES * HIDDEN];     // q
__device__ float g_k[N_NODES * HIDDEN];     // k; later reused as t1 (silu output)
__device__ float g_v[N_NODES * HIDDEN];
__device__ float g_ex[N_EDGES * HEADS];     // exp(logit) per (edge, head)
__device__ float g_s[N_NODES * HEADS];
__device__ float g_U[N_NODES * HIDDEN];
__device__ float g_disp[N_NODES * 3];

// ---------------- packed-f32x2 helpers ----------------
__device__ __forceinline__ uint64_t pack_dup(float a) {
    uint64_t r;
    asm("mov.b64 %0, {%1, %1};" : "=l"(r) : "f"(a));
    return r;
}
__device__ __forceinline__ void fma2(uint64_t& c, uint64_t a, uint64_t b) {
    asm("fma.rn.f32x2 %0, %1, %2, %0;" : "+l"(c) : "l"(a), "l"(b));
}
__device__ __forceinline__ float2 unpack2(uint64_t p) {
    float lo, hi;
    asm("mov.b64 {%0, %1}, %2;" : "=f"(lo), "=f"(hi) : "l"(p));
    return make_float2(lo, hi);
}

// ---------------- FFMA2 GEMM: C[M,128] = A[M,128] @ W[128,128] ----------------
// 128x128 CTA tile, 256 thr, 8x8 microtile, KC=32 k-chunks.
// EPI: 0 plain, 1 +residual, 2 silu. SCALE_A: row scaled by rcp(max(g_s,1e-9)).
// FUSE_INIT: CTAs also grid-stride-zero g_U/g_s/g_disp (QKV launch only).
#define KC 32

template <int EPI, bool SCALE_A, bool FUSE_INIT>
__global__ __launch_bounds__(256, 2) void gemm128(
    const float* __restrict__ A,
    const float* __restrict__ B0, const float* __restrict__ B1, const float* __restrict__ B2,
    const float* __restrict__ bias0, const float* __restrict__ bias1, const float* __restrict__ bias2,
    const float* __restrict__ res,
    float* __restrict__ out0, float* __restrict__ out1, float* __restrict__ out2,
    int M)
{
    __shared__ float As[KC][132];     // transposed: As[k][m]
    __shared__ float Bs[KC][HIDDEN];

    if (FUSE_INIT) {
        // zero g_U (1.6M float4), g_s (100K float4), g_disp (37.5K float4)
        int nthr = gridDim.x * gridDim.y * 256;
        int gtid = (blockIdx.y * gridDim.x + blockIdx.x) * 256 + threadIdx.x;
        float4 z = make_float4(0.f, 0.f, 0.f, 0.f);
        for (int i = gtid; i < N_NODES * HIDDEN / 4; i += nthr) ((float4*)g_U)[i] = z;
        for (int i = gtid; i < N_NODES * HEADS / 4; i += nthr) ((float4*)g_s)[i] = z;
        for (int i = gtid; i < N_NODES * 3 / 4; i += nthr) ((float4*)g_disp)[i] = z;
    }

    const float* B    = (blockIdx.y == 0) ? B0    : (blockIdx.y == 1) ? B1    : B2;
    const float* bias = (blockIdx.y == 0) ? bias0 : (blockIdx.y == 1) ? bias1 : bias2;
    float*       out  = (blockIdx.y == 0) ? out0  : (blockIdx.y == 1) ? out1  : out2;

    const int t   = threadIdx.x;
    const int tx  = t & 15;           // col group (8 cols = 4 packed pairs)
    const int ty  = t >> 4;           // row group (8 rows)
    const int row0 = blockIdx.x * 128;

    uint64_t acc[8][4];
#pragma unroll
    for (int i = 0; i < 8; i++)
#pragma unroll
        for (int j = 0; j < 4; j++) acc[i][j] = 0ull;

    for (int kt = 0; kt < HIDDEN; kt += KC) {
        // A tile: 128 rows x 32 k, stored transposed (1024 float4 loads)
#pragma unroll
        for (int it = 0; it < 4; it++) {
            int idx = t + it * 256;            // 0..1023
            int r   = idx >> 3;                // row 0..127
            int c4  = idx & 7;                 // float4 within 32 k
            float4 val = make_float4(0.f, 0.f, 0.f, 0.f);
            int gr = row0 + r;
            if (gr < M) {
                val = *(const float4*)(A + gr * HIDDEN + kt + c4 * 4);
                if (SCALE_A) {
                    float inv = __frcp_rn(fmaxf(g_s[gr * HEADS + ((kt + c4 * 4) >> 4)], 1e-9f));
                    val.x *= inv; val.y *= inv; val.z *= inv; val.w *= inv;
                }
            }
            As[c4 * 4 + 0][r] = val.x;
            As[c4 * 4 + 1][r] = val.y;
            As[c4 * 4 + 2][r] = val.z;
            As[c4 * 4 + 3][r] = val.w;
        }
        // B tile: 32 x 128 (1024 float4 loads)
#pragma unroll
        for (int it = 0; it < 4; it++) {
            int idx = t + it * 256;
            int r   = idx >> 5;                // 0..31
            int c4  = idx & 31;
            *(float4*)(&Bs[r][c4 * 4]) = *(const float4*)(B + (kt + r) * HIDDEN + c4 * 4);
        }
        __syncthreads();

#pragma unroll
        for (int kk = 0; kk < KC; kk++) {
            float4 a0 = *(float4*)(&As[kk][ty * 8]);
            float4 a1 = *(float4*)(&As[kk][ty * 8 + 4]);
            ulonglong2 b01 = *(ulonglong2*)(&Bs[kk][tx * 8]);
            ulonglong2 b23 = *(ulonglong2*)(&Bs[kk][tx * 8 + 4]);
            uint64_t bp[4] = {b01.x, b01.y, b23.x, b23.y};
            uint64_t ap[8];
            ap[0] = pack_dup(a0.x); ap[1] = pack_dup(a0.y);
            ap[2] = pack_dup(a0.z); ap[3] = pack_dup(a0.w);
            ap[4] = pack_dup(a1.x); ap[5] = pack_dup(a1.y);
            ap[6] = pack_dup(a1.z); ap[7] = pack_dup(a1.w);
#pragma unroll
            for (int i = 0; i < 8; i++)
#pragma unroll
                for (int j = 0; j < 4; j++) fma2(acc[i][j], ap[i], bp[j]);
        }
        __syncthreads();
    }

    // epilogue: 8 rows x 8 cols per thread
#pragma unroll
    for (int i = 0; i < 8; i++) {
        int gr = row0 + ty * 8 + i;
        if (gr >= M) continue;
#pragma unroll
        for (int jj = 0; jj < 2; jj++) {
            int col = tx * 8 + jj * 4;
            float2 p0 = unpack2(acc[i][jj * 2 + 0]);
            float2 p1 = unpack2(acc[i][jj * 2 + 1]);
            float z[4] = {p0.x, p0.y, p1.x, p1.y};
#pragma unroll
            for (int q = 0; q < 4; q++) z[q] += bias[col + q];
            if (EPI == 1) {
                float4 r4 = *(const float4*)(res + gr * HIDDEN + col);
                z[0] += r4.x; z[1] += r4.y; z[2] += r4.z; z[3] += r4.w;
            }
            if (EPI == 2) {
#pragma unroll
                for (int q = 0; q < 4; q++) z[q] = z[q] / (1.f + __expf(-z[q]));
            }
            *(float4*)(out + gr * HIDDEN + col) = make_float4(z[0], z[1], z[2], z[3]);
        }
    }
}

// ---------------- fused edge kernel: logits + exp + s-sum + U scatter ----------------
__global__ __launch_bounds__(512) void k_edge(
    const int* __restrict__ src, const int* __restrict__ dst,
    const float* __restrict__ dist,
    const float* __restrict__ Wd, const float* __restrict__ bd)
{
    int t = blockIdx.x * blockDim.x + threadIdx.x;
    if (t >= N_EDGES * HEADS) return;
    int e = t >> 3, h = t & 7;
    int sn = src[e], dn = dst[e];

    const float4* qp = (const float4*)(g_q + sn * HIDDEN + h * HDIM);
    const float4* kp = (const float4*)(g_k + dn * HIDDEN + h * HDIM);
    float acc = 0.f;
#pragma unroll
    for (int i = 0; i < 4; i++) {
        float4 a = qp[i], b = kp[i];
        acc += a.x * b.x + a.y * b.y + a.z * b.z + a.w * b.w;
    }
    float dd = dist[e];
    float lg = acc * 0.25f - (dd * dd * Wd[h] + bd[h]);
    float ex = __expf(lg);
    g_ex[t] = ex;

    atomicAdd(&g_s[sn * HEADS + h], ex);

    const float4* vp = (const float4*)(g_v + dn * HIDDEN + h * HDIM);
    float* up = g_U + sn * HIDDEN + h * HDIM;
#pragma unroll
    for (int i = 0; i < 4; i++) {
        float4 vv = vp[i];
        float x0 = vv.x * ex, x1 = vv.y * ex, x2 = vv.z * ex, x3 = vv.w * ex;
        asm volatile("red.global.add.v4.f32 [%0], {%1,%2,%3,%4};"
                     :: "l"(up + i * 4), "f"(x0), "f"(x1), "f"(x2), "f"(x3)
                     : "memory");
    }
}

// ---------------- displacement scatter ----------------
__global__ void k_disp(const int* __restrict__ src, const int* __restrict__ dst,
                       const float* __restrict__ x)
{
    int e = blockIdx.x * blockDim.x + threadIdx.x;
    if (e >= N_EDGES) return;
    int sn = src[e], dn = dst[e];

    const float4* exp4 = (const float4*)(g_ex + e * 8);
    const float4* sp   = (const float4*)(g_s + sn * 8);
    float4 e0 = exp4[0], e1 = exp4[1];
    float4 s0 = sp[0],   s1 = sp[1];

    float wsum =
        e0.x / fmaxf(s0.x, 1e-9f) + e0.y / fmaxf(s0.y, 1e-9f) +
        e0.z / fmaxf(s0.z, 1e-9f) + e0.w / fmaxf(s0.w, 1e-9f) +
        e1.x / fmaxf(s1.x, 1e-9f) + e1.y / fmaxf(s1.y, 1e-9f) +
        e1.z / fmaxf(s1.z, 1e-9f) + e1.w / fmaxf(s1.w, 1e-9f);
    float wmean = wsum * 0.125f;

#pragma unroll
    for (int c = 0; c < 3; c++)
        atomicAdd(&g_disp[sn * 3 + c], (x[dn * 3 + c] - x[sn * 3 + c]) * wmean);
}

// ---------------- gate + x_out ----------------
__global__ void k_gate(const float* __restrict__ Wg2, const float* __restrict__ bg2,
                       const float* __restrict__ x, float* __restrict__ out)
{
    int gt   = blockIdx.x * blockDim.x + threadIdx.x;
    int node = gt >> 5;
    int lane = threadIdx.x & 31;
    if (node >= N_NODES) return;

    float4 a = *(const float4*)(g_k + node * HIDDEN + lane * 4);  // t1
    float4 b = *(const float4*)(Wg2 + lane * 4);
    float p = a.x * b.x + a.y * b.y + a.z * b.z + a.w * b.w;
#pragma unroll
    for (int off = 16; off; off >>= 1) p += __shfl_xor_sync(0xffffffffu, p, off);
    float g = tanhf(p + bg2[0]);
    if (lane < 3) {
        out[N_NODES * HIDDEN + node * 3 + lane] =
            x[node * 3 + lane] + g * g_disp[node * 3 + lane];
    }
}

// ---------------- launch ----------------
extern "C" void kernel_launch(void* const* d_in, const int* in_sizes, int n_in,
                              void* d_out, int out_size)
{
    (void)in_sizes; (void)n_in; (void)out_size;
    const float* h    = (const float*)d_in[0];
    const float* x    = (const float*)d_in[1];
    const int*   src  = (const int*)  d_in[2];
    const int*   dst  = (const int*)  d_in[3];
    const float* dist = (const float*)d_in[4];
    const float* Wq = (const float*)d_in[5],  *bq = (const float*)d_in[6];
    const float* Wk = (const float*)d_in[7],  *bk = (const float*)d_in[8];
    const float* Wv = (const float*)d_in[9],  *bv = (const float*)d_in[10];
    const float* Wo = (const float*)d_in[11], *bo = (const float*)d_in[12];
    const float* Wd = (const float*)d_in[13], *bd = (const float*)d_in[14];
    const float* Wg1 = (const float*)d_in[15], *bg1 = (const float*)d_in[16];
    const float* Wg2 = (const float*)d_in[17], *bg2 = (const float*)d_in[18];
    float* out = (float*)d_out;

    void *pq, *pk, *pv, *pU;
    cudaGetSymbolAddress(&pq, g_q);
    cudaGetSymbolAddress(&pk, g_k);
    cudaGetSymbolAddress(&pv, g_v);
    cudaGetSymbolAddress(&pU, g_U);
    float* fq = (float*)pq; float* fk = (float*)pk; float* fv = (float*)pv;
    float* fU = (float*)pU;

    const int B = 256;
    int gblocks = (N_NODES + 127) / 128;

    // fused QKV projection + scratch zero-init (FUSE_INIT)
    {
        dim3 grid(gblocks, 3);
        gemm128<0, false, true><<<grid, 256>>>(h, Wq, Wk, Wv, bq, bk, bv,
                                               nullptr, fq, fk, fv, N_NODES);
    }

    // edge phase (atomic scatter)
    int eht = N_EDGES * HEADS;
    k_edge<<<(eht + 511) / 512, 512>>>(src, dst, dist, Wd, bd);
    k_disp<<<(N_EDGES + B - 1) / B, B>>>(src, dst, x);

    // Wo GEMM normalizes g_U by rcp(s) on the fly
    {
        dim3 grid(gblocks, 1);
        gemm128<1, true, false><<<grid, 256>>>(fU, Wo, Wo, Wo, bo, bo, bo,
                                               h, out, out, out, N_NODES);
        gemm128<2, false, false><<<grid, 256>>>(out, Wg1, Wg1, Wg1, bg1, bg1, bg1,
                                                nullptr, fk, fk, fk, N_NODES);
    }
    k_gate<<<(N_NODES * 32 + B - 1) / B, B>>>(Wg2, bg2, x, out);
}

// round 10
// speedup vs baseline: 1.0148x; 1.0148x over previous
#include <cuda_runtime.h>
#include <cuda_bf16.h>
#include <cstdint>

#define N_NODES 50000
#define N_EDGES 500000
#define HIDDEN  128
#define HEADS   8
#define HDIM    16

// ---------------- static device scratch ----------------
__device__ float g_q[N_NODES * HIDDEN];     // q
__device__ float g_k[N_NODES * HIDDEN];     // k
__device__ float g_v[N_NODES * HIDDEN];
__device__ float g_ex[N_EDGES * HEADS];     // exp(logit) per (edge, head)
__device__ float g_s[N_NODES * HEADS];
__device__ float g_U[N_NODES * HIDDEN];
__device__ float g_disp[N_NODES * 3];

// ---------------- packed-f32x2 helpers ----------------
__device__ __forceinline__ uint64_t pack_dup(float a) {
    uint64_t r;
    asm("mov.b64 %0, {%1, %1};" : "=l"(r) : "f"(a));
    return r;
}
__device__ __forceinline__ uint64_t pack2(float lo, float hi) {
    uint64_t r;
    asm("mov.b64 %0, {%1, %2};" : "=l"(r) : "f"(lo), "f"(hi));
    return r;
}
__device__ __forceinline__ void fma2(uint64_t& c, uint64_t a, uint64_t b) {
    asm("fma.rn.f32x2 %0, %1, %2, %0;" : "+l"(c) : "l"(a), "l"(b));
}
__device__ __forceinline__ float2 unpack2(uint64_t p) {
    float lo, hi;
    asm("mov.b64 {%0, %1}, %2;" : "=f"(lo), "=f"(hi) : "l"(p));
    return make_float2(lo, hi);
}

#define KC 16

// ================= QKV GEMM (FFMA2, KC=16) + fused scratch init =================
__global__ __launch_bounds__(256, 2) void gemm_qkv(
    const float* __restrict__ A,
    const float* __restrict__ B0, const float* __restrict__ B1, const float* __restrict__ B2,
    const float* __restrict__ bias0, const float* __restrict__ bias1, const float* __restrict__ bias2,
    float* __restrict__ out0, float* __restrict__ out1, float* __restrict__ out2,
    int M)
{
    __shared__ float As[KC][132];
    __shared__ float Bs[KC][HIDDEN];

    {   // fused zero-init of g_U / g_s / g_disp
        int nthr = gridDim.x * gridDim.y * 256;
        int gtid = (blockIdx.y * gridDim.x + blockIdx.x) * 256 + threadIdx.x;
        float4 z = make_float4(0.f, 0.f, 0.f, 0.f);
        for (int i = gtid; i < N_NODES * HIDDEN / 4; i += nthr) ((float4*)g_U)[i] = z;
        for (int i = gtid; i < N_NODES * HEADS / 4; i += nthr) ((float4*)g_s)[i] = z;
        for (int i = gtid; i < N_NODES * 3 / 4; i += nthr) ((float4*)g_disp)[i] = z;
    }

    const float* B    = (blockIdx.y == 0) ? B0    : (blockIdx.y == 1) ? B1    : B2;
    const float* bias = (blockIdx.y == 0) ? bias0 : (blockIdx.y == 1) ? bias1 : bias2;
    float*       out  = (blockIdx.y == 0) ? out0  : (blockIdx.y == 1) ? out1  : out2;

    const int t = threadIdx.x, tx = t & 15, ty = t >> 4;
    const int row0 = blockIdx.x * 128;

    uint64_t acc[8][4];
#pragma unroll
    for (int i = 0; i < 8; i++)
#pragma unroll
        for (int j = 0; j < 4; j++) acc[i][j] = 0ull;

    for (int kt = 0; kt < HIDDEN; kt += KC) {
#pragma unroll
        for (int it = 0; it < 2; it++) {
            int idx = t + it * 256;
            int r = idx >> 2, c4 = idx & 3;
            float4 val = make_float4(0.f, 0.f, 0.f, 0.f);
            int gr = row0 + r;
            if (gr < M) val = *(const float4*)(A + gr * HIDDEN + kt + c4 * 4);
            As[c4 * 4 + 0][r] = val.x; As[c4 * 4 + 1][r] = val.y;
            As[c4 * 4 + 2][r] = val.z; As[c4 * 4 + 3][r] = val.w;
        }
#pragma unroll
        for (int it = 0; it < 2; it++) {
            int idx = t + it * 256;
            int r = idx >> 5, c4 = idx & 31;
            *(float4*)(&Bs[r][c4 * 4]) = *(const float4*)(B + (kt + r) * HIDDEN + c4 * 4);
        }
        __syncthreads();

#pragma unroll
        for (int kk = 0; kk < KC; kk++) {
            float4 a0 = *(float4*)(&As[kk][ty * 8]);
            float4 a1 = *(float4*)(&As[kk][ty * 8 + 4]);
            ulonglong2 b01 = *(ulonglong2*)(&Bs[kk][tx * 8]);
            ulonglong2 b23 = *(ulonglong2*)(&Bs[kk][tx * 8 + 4]);
            uint64_t bp[4] = {b01.x, b01.y, b23.x, b23.y};
            uint64_t ap[8];
            ap[0] = pack_dup(a0.x); ap[1] = pack_dup(a0.y);
            ap[2] = pack_dup(a0.z); ap[3] = pack_dup(a0.w);
            ap[4] = pack_dup(a1.x); ap[5] = pack_dup(a1.y);
            ap[6] = pack_dup(a1.z); ap[7] = pack_dup(a1.w);
#pragma unroll
            for (int i = 0; i < 8; i++)
#pragma unroll
                for (int j = 0; j < 4; j++) fma2(acc[i][j], ap[i], bp[j]);
        }
        __syncthreads();
    }

#pragma unroll
    for (int i = 0; i < 8; i++) {
        int gr = row0 + ty * 8 + i;
        if (gr >= M) continue;
#pragma unroll
        for (int jj = 0; jj < 2; jj++) {
            int col = tx * 8 + jj * 4;
            float2 p0 = unpack2(acc[i][jj * 2 + 0]);
            float2 p1 = unpack2(acc[i][jj * 2 + 1]);
            float4 o = make_float4(p0.x + bias[col], p0.y + bias[col + 1],
                                   p1.x + bias[col + 2], p1.y + bias[col + 3]);
            *(float4*)(out + gr * HIDDEN + col) = o;
        }
    }
}

// ================= fused node epilogue: Wo-GEMM + Wg1-GEMM + gate + x_out =================
// Stage1: T = (g_U * rcp(s)) @ Wo + bo + h  -> write h_out to out, keep T in regs
// Stage2: t1 = silu(T @ Wg1 + bg1)          -> regs (A fed from stage-1 regs via SMEM)
// Stage3: gate = tanh(t1 . Wg2 + bg2); x_out = x + gate * disp
__global__ __launch_bounds__(256, 2) void k_node_out(
    const float* __restrict__ Wo, const float* __restrict__ bo,
    const float* __restrict__ Wg1, const float* __restrict__ bg1,
    const float* __restrict__ Wg2, const float* __restrict__ bg2,
    const float* __restrict__ hres, const float* __restrict__ x,
    float* __restrict__ out, int M)
{
    __shared__ float As[KC][132];
    __shared__ float Bs[KC][HIDDEN];

    const int t = threadIdx.x, tx = t & 15, ty = t >> 4;
    const int row0 = blockIdx.x * 128;

    uint64_t acc[8][4];
#pragma unroll
    for (int i = 0; i < 8; i++)
#pragma unroll
        for (int j = 0; j < 4; j++) acc[i][j] = 0ull;

    // ---- stage 1: T = hupd @ Wo ----
    for (int kt = 0; kt < HIDDEN; kt += KC) {
#pragma unroll
        for (int it = 0; it < 2; it++) {
            int idx = t + it * 256;
            int r = idx >> 2, c4 = idx & 3;
            float4 val = make_float4(0.f, 0.f, 0.f, 0.f);
            int gr = row0 + r;
            if (gr < M) {
                val = *(const float4*)(g_U + gr * HIDDEN + kt + c4 * 4);
                float inv = __frcp_rn(fmaxf(g_s[gr * HEADS + ((kt + c4 * 4) >> 4)], 1e-9f));
                val.x *= inv; val.y *= inv; val.z *= inv; val.w *= inv;
            }
            As[c4 * 4 + 0][r] = val.x; As[c4 * 4 + 1][r] = val.y;
            As[c4 * 4 + 2][r] = val.z; As[c4 * 4 + 3][r] = val.w;
        }
#pragma unroll
        for (int it = 0; it < 2; it++) {
            int idx = t + it * 256;
            int r = idx >> 5, c4 = idx & 31;
            *(float4*)(&Bs[r][c4 * 4]) = *(const float4*)(Wo + (kt + r) * HIDDEN + c4 * 4);
        }
        __syncthreads();

#pragma unroll
        for (int kk = 0; kk < KC; kk++) {
            float4 a0 = *(float4*)(&As[kk][ty * 8]);
            float4 a1 = *(float4*)(&As[kk][ty * 8 + 4]);
            ulonglong2 b01 = *(ulonglong2*)(&Bs[kk][tx * 8]);
            ulonglong2 b23 = *(ulonglong2*)(&Bs[kk][tx * 8 + 4]);
            uint64_t bp[4] = {b01.x, b01.y, b23.x, b23.y};
            uint64_t ap[8];
            ap[0] = pack_dup(a0.x); ap[1] = pack_dup(a0.y);
            ap[2] = pack_dup(a0.z); ap[3] = pack_dup(a0.w);
            ap[4] = pack_dup(a1.x); ap[5] = pack_dup(a1.y);
            ap[6] = pack_dup(a1.z); ap[7] = pack_dup(a1.w);
#pragma unroll
            for (int i = 0; i < 8; i++)
#pragma unroll
                for (int j = 0; j < 4; j++) fma2(acc[i][j], ap[i], bp[j]);
        }
        __syncthreads();
    }

    // stage-1 epilogue: h_out = acc + bo + h; write to out; repack into acc
#pragma unroll
    for (int i = 0; i < 8; i++) {
        int gr = row0 + ty * 8 + i;
        bool valid = (gr < M);
#pragma unroll
        for (int jj = 0; jj < 2; jj++) {
            int col = tx * 8 + jj * 4;
            float2 p0 = unpack2(acc[i][jj * 2 + 0]);
            float2 p1 = unpack2(acc[i][jj * 2 + 1]);
            float z0 = p0.x + bo[col],     z1 = p0.y + bo[col + 1];
            float z2 = p1.x + bo[col + 2], z3 = p1.y + bo[col + 3];
            if (valid) {
                float4 r4 = *(const float4*)(hres + gr * HIDDEN + col);
                z0 += r4.x; z1 += r4.y; z2 += r4.z; z3 += r4.w;
                *(float4*)(out + gr * HIDDEN + col) = make_float4(z0, z1, z2, z3);
            }
            acc[i][jj * 2 + 0] = pack2(z0, z1);
            acc[i][jj * 2 + 1] = pack2(z2, z3);
        }
    }

    // ---- stage 2: t1 = silu(T @ Wg1 + bg1), A fed from acc regs ----
    uint64_t acc2[8][4];
#pragma unroll
    for (int i = 0; i < 8; i++)
#pragma unroll
        for (int j = 0; j < 4; j++) acc2[i][j] = 0ull;

    for (int c = 0; c < HIDDEN / KC; c++) {
        __syncthreads();      // protect As/Bs reuse
        // threads owning cols [16c, 16c+16) write their acc block into As (transposed)
        if ((tx >> 1) == c) {
            int cb = (tx & 1) * 8;   // local col base within chunk
#pragma unroll
            for (int i = 0; i < 8; i++) {
                int row = ty * 8 + i;
#pragma unroll
                for (int j = 0; j < 4; j++) {
                    float2 p = unpack2(acc[i][j]);
                    As[cb + j * 2 + 0][row] = p.x;
                    As[cb + j * 2 + 1][row] = p.y;
                }
            }
        }
#pragma unroll
        for (int it = 0; it < 2; it++) {
            int idx = t + it * 256;
            int r = idx >> 5, c4 = idx & 31;
            *(float4*)(&Bs[r][c4 * 4]) = *(const float4*)(Wg1 + (c * KC + r) * HIDDEN + c4 * 4);
        }
        __syncthreads();

#pragma unroll
        for (int kk = 0; kk < KC; kk++) {
            float4 a0 = *(float4*)(&As[kk][ty * 8]);
            float4 a1 = *(float4*)(&As[kk][ty * 8 + 4]);
            ulonglong2 b01 = *(ulonglong2*)(&Bs[kk][tx * 8]);
            ulonglong2 b23 = *(ulonglong2*)(&Bs[kk][tx * 8 + 4]);
            uint64_t bp[4] = {b01.x, b01.y, b23.x, b23.y};
            uint64_t ap[8];
            ap[0] = pack_dup(a0.x); ap[1] = pack_dup(a0.y);
            ap[2] = pack_dup(a0.z); ap[3] = pack_dup(a0.w);
            ap[4] = pack_dup(a1.x); ap[5] = pack_dup(a1.y);
            ap[6] = pack_dup(a1.z); ap[7] = pack_dup(a1.w);
#pragma unroll
            for (int i = 0; i < 8; i++)
#pragma unroll
                for (int j = 0; j < 4; j++) fma2(acc2[i][j], ap[i], bp[j]);
        }
    }

    // ---- stage 3: silu, Wg2 dot (half-warp reduce), tanh gate, x_out ----
    float w2[8];
#pragma unroll
    for (int j = 0; j < 8; j++) w2[j] = Wg2[tx * 8 + j];
    const float bg2v = bg2[0];

#pragma unroll
    for (int i = 0; i < 8; i++) {
        float p = 0.f;
#pragma unroll
        for (int j = 0; j < 4; j++) {
            float2 v = unpack2(acc2[i][j]);
            float t0 = v.x + bg1[tx * 8 + j * 2];
            float t1v = v.y + bg1[tx * 8 + j * 2 + 1];
            t0 = t0 / (1.f + __expf(-t0));
            t1v = t1v / (1.f + __expf(-t1v));
            p = fmaf(t0, w2[j * 2], p);
            p = fmaf(t1v, w2[j * 2 + 1], p);
        }
        // reduce across the 16 tx lanes (same ty = one half-warp)
#pragma unroll
        for (int off = 1; off < 16; off <<= 1)
            p += __shfl_xor_sync(0xffffffffu, p, off);
        if (tx == 0) {
            int gr = row0 + ty * 8 + i;
            if (gr < M) {
                float g = tanhf(p + bg2v);
#pragma unroll
                for (int cc = 0; cc < 3; cc++)
                    out[N_NODES * HIDDEN + gr * 3 + cc] =
                        x[gr * 3 + cc] + g * g_disp[gr * 3 + cc];
            }
        }
    }
}

// ---------------- fused edge kernel ----------------
__global__ __launch_bounds__(512) void k_edge(
    const int* __restrict__ src, const int* __restrict__ dst,
    const float* __restrict__ dist,
    const float* __restrict__ Wd, const float* __restrict__ bd)
{
    int t = blockIdx.x * blockDim.x + threadIdx.x;
    if (t >= N_EDGES * HEADS) return;
    int e = t >> 3, h = t & 7;
    int sn = src[e], dn = dst[e];

    const float4* qp = (const float4*)(g_q + sn * HIDDEN + h * HDIM);
    const float4* kp = (const float4*)(g_k + dn * HIDDEN + h * HDIM);
    float acc = 0.f;
#pragma unroll
    for (int i = 0; i < 4; i++) {
        float4 a = qp[i], b = kp[i];
        acc += a.x * b.x + a.y * b.y + a.z * b.z + a.w * b.w;
    }
    float dd = dist[e];
    float lg = acc * 0.25f - (dd * dd * Wd[h] + bd[h]);
    float ex = __expf(lg);
    g_ex[t] = ex;

    atomicAdd(&g_s[sn * HEADS + h], ex);

    const float4* vp = (const float4*)(g_v + dn * HIDDEN + h * HDIM);
    float* up = g_U + sn * HIDDEN + h * HDIM;
#pragma unroll
    for (int i = 0; i < 4; i++) {
        float4 vv = vp[i];
        float x0 = vv.x * ex, x1 = vv.y * ex, x2 = vv.z * ex, x3 = vv.w * ex;
        asm volatile("red.global.add.v4.f32 [%0], {%1,%2,%3,%4};"
                     :: "l"(up + i * 4), "f"(x0), "f"(x1), "f"(x2), "f"(x3)
                     : "memory");
    }
}

// ---------------- displacement scatter ----------------
__global__ void k_disp(const int* __restrict__ src, const int* __restrict__ dst,
                       const float* __restrict__ x)
{
    int e = blockIdx.x * blockDim.x + threadIdx.x;
    if (e >= N_EDGES) return;
    int sn = src[e], dn = dst[e];

    const float4* exp4 = (const float4*)(g_ex + e * 8);
    const float4* sp   = (const float4*)(g_s + sn * 8);
    float4 e0 = exp4[0], e1 = exp4[1];
    float4 s0 = sp[0],   s1 = sp[1];

    float wsum =
        e0.x / fmaxf(s0.x, 1e-9f) + e0.y / fmaxf(s0.y, 1e-9f) +
        e0.z / fmaxf(s0.z, 1e-9f) + e0.w / fmaxf(s0.w, 1e-9f) +
        e1.x / fmaxf(s1.x, 1e-9f) + e1.y / fmaxf(s1.y, 1e-9f) +
        e1.z / fmaxf(s1.z, 1e-9f) + e1.w / fmaxf(s1.w, 1e-9f);
    float wmean = wsum * 0.125f;

#pragma unroll
    for (int c = 0; c < 3; c++)
        atomicAdd(&g_disp[sn * 3 + c], (x[dn * 3 + c] - x[sn * 3 + c]) * wmean);
}

// ---------------- launch ----------------
extern "C" void kernel_launch(void* const* d_in, const int* in_sizes, int n_in,
                              void* d_out, int out_size)
{
    (void)in_sizes; (void)n_in; (void)out_size;
    const float* h    = (const float*)d_in[0];
    const float* x    = (const float*)d_in[1];
    const int*   src  = (const int*)  d_in[2];
    const int*   dst  = (const int*)  d_in[3];
    const float* dist = (const float*)d_in[4];
    const float* Wq = (const float*)d_in[5],  *bq = (const float*)d_in[6];
    const float* Wk = (const float*)d_in[7],  *bk = (const float*)d_in[8];
    const float* Wv = (const float*)d_in[9],  *bv = (const float*)d_in[10];
    const float* Wo = (const float*)d_in[11], *bo = (const float*)d_in[12];
    const float* Wd = (const float*)d_in[13], *bd = (const float*)d_in[14];
    const float* Wg1 = (const float*)d_in[15], *bg1 = (const float*)d_in[16];
    const float* Wg2 = (const float*)d_in[17], *bg2 = (const float*)d_in[18];
    float* out = (float*)d_out;

    void *pq, *pk, *pv;
    cudaGetSymbolAddress(&pq, g_q);
    cudaGetSymbolAddress(&pk, g_k);
    cudaGetSymbolAddress(&pv, g_v);
    float* fq = (float*)pq; float* fk = (float*)pk; float* fv = (float*)pv;

    const int B = 256;
    int gblocks = (N_NODES + 127) / 128;

    // fused QKV projection + scratch zero-init
    {
        dim3 grid(gblocks, 3);
        gemm_qkv<<<grid, 256>>>(h, Wq, Wk, Wv, bq, bk, bv, fq, fk, fv, N_NODES);
    }

    // edge phase
    int eht = N_EDGES * HEADS;
    k_edge<<<(eht + 511) / 512, 512>>>(src, dst, dist, Wd, bd);
    k_disp<<<(N_EDGES + B - 1) / B, B>>>(src, dst, x);

    // fused node epilogue: Wo GEMM + Wg1 GEMM + gate + both outputs
    k_node_out<<<gblocks, 256>>>(Wo, bo, Wg1, bg1, Wg2, bg2, h, x, out, N_NODES);
}

// round 11
// speedup vs baseline: 1.0394x; 1.0242x over previous
#include <cuda_runtime.h>
#include <cuda_bf16.h>
#include <cstdint>

#define N_NODES 50000
#define N_EDGES 500000
#define HIDDEN  128
#define HEADS   8
#define HDIM    16

// ---------------- static device scratch ----------------
__device__ float g_q[N_NODES * HIDDEN];
__device__ float g_k[N_NODES * HIDDEN];
__device__ float g_v[N_NODES * HIDDEN];
__device__ float g_ex[N_EDGES * HEADS];
__device__ float g_s[N_NODES * HEADS];
__device__ float g_U[N_NODES * HIDDEN];
__device__ float g_disp[N_NODES * 3];

// ---------------- packed-f32x2 + cp.async helpers ----------------
__device__ __forceinline__ uint64_t pack_dup(float a) {
    uint64_t r;
    asm("mov.b64 %0, {%1, %1};" : "=l"(r) : "f"(a));
    return r;
}
__device__ __forceinline__ void fma2(uint64_t& c, uint64_t a, uint64_t b) {
    asm("fma.rn.f32x2 %0, %1, %2, %0;" : "+l"(c) : "l"(a), "l"(b));
}
__device__ __forceinline__ float2 unpack2(uint64_t p) {
    float lo, hi;
    asm("mov.b64 {%0, %1}, %2;" : "=f"(lo), "=f"(hi) : "l"(p));
    return make_float2(lo, hi);
}
__device__ __forceinline__ uint32_t smem_u32(const void* p) {
    uint32_t a;
    asm("{ .reg .u64 t; cvta.to.shared.u64 t, %1; cvt.u32.u64 %0, t; }" : "=r"(a) : "l"(p));
    return a;
}
__device__ __forceinline__ void cp16(uint32_t dst, const void* src) {
    asm volatile("cp.async.ca.shared.global [%0], [%1], 16;" :: "r"(dst), "l"(src) : "memory");
}
__device__ __forceinline__ void cp_commit() { asm volatile("cp.async.commit_group;" ::: "memory"); }
__device__ __forceinline__ void cp_wait1() { asm volatile("cp.async.wait_group 1;" ::: "memory"); }
__device__ __forceinline__ void cp_wait0() { asm volatile("cp.async.wait_group 0;" ::: "memory"); }

// ---------------- shared GEMM core: C[128,128] tile, cp.async double-buffered ----------------
struct __align__(16) SmemBufs {
    float As[2][128][20];   // row-major A chunk, 80B row stride
    float Bs[2][16][128];
};

__device__ __forceinline__ void load_chunk(SmemBufs& S, int buf, int c,
    const float* __restrict__ A, const float* __restrict__ B, int row0, int M, int t)
{
#pragma unroll
    for (int it = 0; it < 2; it++) {
        int s = t + it * 256;
        int r = s >> 2, q = s & 3;
        int gr = min(row0 + r, M - 1);
        cp16(smem_u32(&S.As[buf][r][q * 4]), A + gr * HIDDEN + c * 16 + q * 4);
    }
#pragma unroll
    for (int it = 0; it < 2; it++) {
        int s = t + it * 256;
        int r = s >> 5, q = s & 31;
        cp16(smem_u32(&S.Bs[buf][r][q * 4]), B + (c * 16 + r) * HIDDEN + q * 4);
    }
}

template <bool SCALE>
__device__ __forceinline__ void run_gemm(SmemBufs& S,
    const float* __restrict__ A, const float* __restrict__ B,
    int row0, int M, int t, int tx, int ty, uint64_t acc[8][4])
{
#pragma unroll
    for (int i = 0; i < 8; i++)
#pragma unroll
        for (int j = 0; j < 4; j++) acc[i][j] = 0ull;

    load_chunk(S, 0, 0, A, B, row0, M, t);
    cp_commit();

    for (int c = 0; c < 8; c++) {
        if (c < 7) { load_chunk(S, (c + 1) & 1, c + 1, A, B, row0, M, t); cp_commit(); }
        if (c < 7) cp_wait1(); else cp_wait0();
        __syncthreads();

        float inv[8];
        if (SCALE) {
#pragma unroll
            for (int i = 0; i < 8; i++) {
                int gr = min(row0 + ty * 8 + i, M - 1);
                inv[i] = __frcp_rn(fmaxf(g_s[gr * HEADS + c], 1e-9f));
            }
        }

        const int buf = c & 1;
#pragma unroll
        for (int kk = 0; kk < 16; kk++) {
            ulonglong2 b01 = *(ulonglong2*)(&S.Bs[buf][kk][tx * 8]);
            ulonglong2 b23 = *(ulonglong2*)(&S.Bs[buf][kk][tx * 8 + 4]);
            uint64_t bp[4] = {b01.x, b01.y, b23.x, b23.y};
            uint64_t ap[8];
#pragma unroll
            for (int i = 0; i < 8; i++) {
                float a = S.As[buf][ty * 8 + i][kk];
                if (SCALE) a *= inv[i];
                ap[i] = pack_dup(a);
            }
#pragma unroll
            for (int i = 0; i < 8; i++)
#pragma unroll
                for (int j = 0; j < 4; j++) fma2(acc[i][j], ap[i], bp[j]);
        }
        __syncthreads();
    }
}

// ================= QKV GEMM + fused scratch init =================
__global__ __launch_bounds__(256, 2) void gemm_qkv(
    const float* __restrict__ A,
    const float* __restrict__ B0, const float* __restrict__ B1, const float* __restrict__ B2,
    const float* __restrict__ bias0, const float* __restrict__ bias1, const float* __restrict__ bias2,
    float* __restrict__ out0, float* __restrict__ out1, float* __restrict__ out2,
    int M)
{
    __shared__ SmemBufs S;

    {   // fused zero-init of g_U / g_s / g_disp
        int nthr = gridDim.x * gridDim.y * 256;
        int gtid = (blockIdx.y * gridDim.x + blockIdx.x) * 256 + threadIdx.x;
        float4 z = make_float4(0.f, 0.f, 0.f, 0.f);
        for (int i = gtid; i < N_NODES * HIDDEN / 4; i += nthr) ((float4*)g_U)[i] = z;
        for (int i = gtid; i < N_NODES * HEADS / 4; i += nthr) ((float4*)g_s)[i] = z;
        for (int i = gtid; i < N_NODES * 3 / 4; i += nthr) ((float4*)g_disp)[i] = z;
    }

    const float* B    = (blockIdx.y == 0) ? B0    : (blockIdx.y == 1) ? B1    : B2;
    const float* bias = (blockIdx.y == 0) ? bias0 : (blockIdx.y == 1) ? bias1 : bias2;
    float*       out  = (blockIdx.y == 0) ? out0  : (blockIdx.y == 1) ? out1  : out2;

    const int t = threadIdx.x, tx = t & 15, ty = t >> 4;
    const int row0 = blockIdx.x * 128;

    uint64_t acc[8][4];
    run_gemm<false>(S, A, B, row0, M, t, tx, ty, acc);

#pragma unroll
    for (int i = 0; i < 8; i++) {
        int gr = row0 + ty * 8 + i;
        if (gr >= M) continue;
#pragma unroll
        for (int jj = 0; jj < 2; jj++) {
            int col = tx * 8 + jj * 4;
            float2 p0 = unpack2(acc[i][jj * 2 + 0]);
            float2 p1 = unpack2(acc[i][jj * 2 + 1]);
            *(float4*)(out + gr * HIDDEN + col) =
                make_float4(p0.x + bias[col], p0.y + bias[col + 1],
                            p1.x + bias[col + 2], p1.y + bias[col + 3]);
        }
    }
}

// ================= fused node epilogue =================
// Stage1: h_out = (g_U*rcp(s)) @ Wo + bo + h  -> STG to out
// Stage2: t1 = silu(h_out @ Wg1 + bg1)  (A re-read from out via cp.async, CTA-local)
// Stage3: gate = tanh(t1 . Wg2 + bg2); x_out = x + gate*disp
__global__ __launch_bounds__(256, 2) void k_node_out(
    const float* __restrict__ Wo, const float* __restrict__ bo,
    const float* __restrict__ Wg1, const float* __restrict__ bg1,
    const float* __restrict__ Wg2, const float* __restrict__ bg2,
    const float* __restrict__ hres, const float* __restrict__ x,
    float* __restrict__ out, int M)
{
    __shared__ SmemBufs S;
    const int t = threadIdx.x, tx = t & 15, ty = t >> 4;
    const int row0 = blockIdx.x * 128;

    uint64_t acc[8][4];

    // ---- stage 1 ----
    run_gemm<true>(S, g_U, Wo, row0, M, t, tx, ty, acc);
#pragma unroll
    for (int i = 0; i < 8; i++) {
        int gr = row0 + ty * 8 + i;
        if (gr >= M) continue;
#pragma unroll
        for (int jj = 0; jj < 2; jj++) {
            int col = tx * 8 + jj * 4;
            float2 p0 = unpack2(acc[i][jj * 2 + 0]);
            float2 p1 = unpack2(acc[i][jj * 2 + 1]);
            float4 r4 = *(const float4*)(hres + gr * HIDDEN + col);
            *(float4*)(out + gr * HIDDEN + col) =
                make_float4(p0.x + bo[col] + r4.x, p0.y + bo[col + 1] + r4.y,
                            p1.x + bo[col + 2] + r4.z, p1.y + bo[col + 3] + r4.w);
        }
    }
    __syncthreads();   // h_out visible CTA-wide before stage-2 reads

    // ---- stage 2 ----
    run_gemm<false>(S, out, Wg1, row0, M, t, tx, ty, acc);

    // ---- stage 3 ----
    float w2[8];
#pragma unroll
    for (int j = 0; j < 8; j++) w2[j] = Wg2[tx * 8 + j];
    const float bg2v = bg2[0];

#pragma unroll
    for (int i = 0; i < 8; i++) {
        float p = 0.f;
#pragma unroll
        for (int j = 0; j < 4; j++) {
            float2 v = unpack2(acc[i][j]);
            float t0 = v.x + bg1[tx * 8 + j * 2];
            float t1v = v.y + bg1[tx * 8 + j * 2 + 1];
            t0 = t0 / (1.f + __expf(-t0));
            t1v = t1v / (1.f + __expf(-t1v));
            p = fmaf(t0, w2[j * 2], p);
            p = fmaf(t1v, w2[j * 2 + 1], p);
        }
#pragma unroll
        for (int off = 1; off < 16; off <<= 1)
            p += __shfl_xor_sync(0xffffffffu, p, off);
        if (tx == 0) {
            int gr = row0 + ty * 8 + i;
            if (gr < M) {
                float g = tanhf(p + bg2v);
#pragma unroll
                for (int cc = 0; cc < 3; cc++)
                    out[N_NODES * HIDDEN + gr * 3 + cc] =
                        x[gr * 3 + cc] + g * g_disp[gr * 3 + cc];
            }
        }
    }
}

// ---------------- fused edge kernel ----------------
__global__ __launch_bounds__(512) void k_edge(
    const int* __restrict__ src, const int* __restrict__ dst,
    const float* __restrict__ dist,
    const float* __restrict__ Wd, const float* __restrict__ bd)
{
    int t = blockIdx.x * blockDim.x + threadIdx.x;
    if (t >= N_EDGES * HEADS) return;
    int e = t >> 3, h = t & 7;
    int sn = src[e], dn = dst[e];

    const float4* qp = (const float4*)(g_q + sn * HIDDEN + h * HDIM);
    const float4* kp = (const float4*)(g_k + dn * HIDDEN + h * HDIM);
    float acc = 0.f;
#pragma unroll
    for (int i = 0; i < 4; i++) {
        float4 a = qp[i], b = kp[i];
        acc += a.x * b.x + a.y * b.y + a.z * b.z + a.w * b.w;
    }
    float dd = dist[e];
    float lg = acc * 0.25f - (dd * dd * Wd[h] + bd[h]);
    float ex = __expf(lg);
    g_ex[t] = ex;

    atomicAdd(&g_s[sn * HEADS + h], ex);

    const float4* vp = (const float4*)(g_v + dn * HIDDEN + h * HDIM);
    float* up = g_U + sn * HIDDEN + h * HDIM;
#pragma unroll
    for (int i = 0; i < 4; i++) {
        float4 vv = vp[i];
        float x0 = vv.x * ex, x1 = vv.y * ex, x2 = vv.z * ex, x3 = vv.w * ex;
        asm volatile("red.global.add.v4.f32 [%0], {%1,%2,%3,%4};"
                     :: "l"(up + i * 4), "f"(x0), "f"(x1), "f"(x2), "f"(x3)
                     : "memory");
    }
}

// ---------------- displacement scatter ----------------
__global__ void k_disp(const int* __restrict__ src, const int* __restrict__ dst,
                       const float* __restrict__ x)
{
    int e = blockIdx.x * blockDim.x + threadIdx.x;
    if (e >= N_EDGES) return;
    int sn = src[e], dn = dst[e];

    const float4* exp4 = (const float4*)(g_ex + e * 8);
    const float4* sp   = (const float4*)(g_s + sn * 8);
    float4 e0 = exp4[0], e1 = exp4[1];
    float4 s0 = sp[0],   s1 = sp[1];

    float wsum =
        e0.x / fmaxf(s0.x, 1e-9f) + e0.y / fmaxf(s0.y, 1e-9f) +
        e0.z / fmaxf(s0.z, 1e-9f) + e0.w / fmaxf(s0.w, 1e-9f) +
        e1.x / fmaxf(s1.x, 1e-9f) + e1.y / fmaxf(s1.y, 1e-9f) +
        e1.z / fmaxf(s1.z, 1e-9f) + e1.w / fmaxf(s1.w, 1e-9f);
    float wmean = wsum * 0.125f;

#pragma unroll
    for (int c = 0; c < 3; c++)
        atomicAdd(&g_disp[sn * 3 + c], (x[dn * 3 + c] - x[sn * 3 + c]) * wmean);
}

// ---------------- launch ----------------
extern "C" void kernel_launch(void* const* d_in, const int* in_sizes, int n_in,
                              void* d_out, int out_size)
{
    (void)in_sizes; (void)n_in; (void)out_size;
    const float* h    = (const float*)d_in[0];
    const float* x    = (const float*)d_in[1];
    const int*   src  = (const int*)  d_in[2];
    const int*   dst  = (const int*)  d_in[3];
    const float* dist = (const float*)d_in[4];
    const float* Wq = (const float*)d_in[5],  *bq = (const float*)d_in[6];
    const float* Wk = (const float*)d_in[7],  *bk = (const float*)d_in[8];
    const float* Wv = (const float*)d_in[9],  *bv = (const float*)d_in[10];
    const float* Wo = (const float*)d_in[11], *bo = (const float*)d_in[12];
    const float* Wd = (const float*)d_in[13], *bd = (const float*)d_in[14];
    const float* Wg1 = (const float*)d_in[15], *bg1 = (const float*)d_in[16];
    const float* Wg2 = (const float*)d_in[17], *bg2 = (const float*)d_in[18];
    float* out = (float*)d_out;

    void *pq, *pk, *pv;
    cudaGetSymbolAddress(&pq, g_q);
    cudaGetSymbolAddress(&pk, g_k);
    cudaGetSymbolAddress(&pv, g_v);
    float* fq = (float*)pq; float* fk = (float*)pk; float* fv = (float*)pv;

    const int B = 256;
    int gblocks = (N_NODES + 127) / 128;

    // fused QKV projection + scratch zero-init
    {
        dim3 grid(gblocks, 3);
        gemm_qkv<<<grid, 256>>>(h, Wq, Wk, Wv, bq, bk, bv, fq, fk, fv, N_NODES);
    }

    // edge phase
    int eht = N_EDGES * HEADS;
    k_edge<<<(eht + 511) / 512, 512>>>(src, dst, dist, Wd, bd);
    k_disp<<<(N_EDGES + B - 1) / B, B>>>(src, dst, x);

    // fused node epilogue: Wo GEMM + Wg1 GEMM + gate + both outputs
    k_node_out<<<gblocks, 256>>>(Wo, bo, Wg1, bg1, Wg2, bg2, h, x, out, N_NODES);
}